// round 15
// baseline (speedup 1.0000x reference)
#include <cuda_runtime.h>
#include <cuda_bf16.h>
#include <math.h>
#include <stdint.h>

#define T_STEPS 2048
#define BATCH   64
#define HID     256
#define GATE4   1024
#define NG      (BATCH*HID)          /* 16384 */
#define REC_BLOCKS 128
#define REC_THREADS 512
#define CHAIN_BLOCKS 8
#define GST     5
#define APAD    40                   /* bf16 row stride: 80B, conflict-free */
#define M_ALL   131072               /* T*B rows of input */

typedef unsigned long long u64;

/* Scratch (device globals: no allocation allowed in kernel_launch) */
__device__ float g_xg[134217728];    /* [T][B][4H] precomputed input gates */
__device__ float g_h[2][NG];         /* double-buffered recurrent h */
__device__ unsigned g_bar16[512];    /* 16 chain barriers, 128B apart */
__device__ unsigned g_done;          /* end-of-kernel reset rendezvous */
__device__ __nv_bfloat16 g_Ahi[M_ALL*256];  /* 67 MB */
__device__ __nv_bfloat16 g_Alo[M_ALL*256];
__device__ __nv_bfloat16 g_Whi[GATE4*256];
__device__ __nv_bfloat16 g_Wlo[GATE4*256];

/* ---- packed f32x2 helpers (recurrence) ---- */
__device__ __forceinline__ u64 ffma2(u64 a, u64 b, u64 c){
  u64 d; asm("fma.rn.f32x2 %0, %1, %2, %3;" : "=l"(d) : "l"(a), "l"(b), "l"(c));
  return d;
}
__device__ __forceinline__ u64 fmul2(u64 a, u64 b){
  u64 d; asm("mul.rn.f32x2 %0, %1, %2;" : "=l"(d) : "l"(a), "l"(b));
  return d;
}
__device__ __forceinline__ u64 fadd2(u64 a, u64 b){
  u64 d; asm("add.rn.f32x2 %0, %1, %2;" : "=l"(d) : "l"(a), "l"(b));
  return d;
}
__device__ __forceinline__ float hadd2(u64 a){
  unsigned lo, hi;
  asm("mov.b64 {%0, %1}, %2;" : "=r"(lo), "=r"(hi) : "l"(a));
  return __uint_as_float(lo) + __uint_as_float(hi);
}
__device__ __forceinline__ float fsigm(float x){
  return __fdividef(1.f, 1.f + __expf(-x));
}
__device__ __forceinline__ float ftanh(float x){
  return __fdividef(2.f, 1.f + __expf(-2.f*x)) - 1.f;
}
__device__ __forceinline__ unsigned ld_acq(const unsigned* p){
  unsigned v;
  asm volatile("ld.global.acquire.gpu.u32 %0, [%1];" : "=r"(v) : "l"(p) : "memory");
  return v;
}
__device__ __forceinline__ void red_rel_add(unsigned* p, unsigned v){
  asm volatile("red.release.gpu.global.add.u32 [%0], %1;" :: "l"(p), "r"(v) : "memory");
}

/* ---- HMMA / ldmatrix helpers (baseline PTX, valid on compute_103) ---- */
__device__ __forceinline__ uint32_t smem_u32(const void* p){
  uint32_t a;
  asm("{ .reg .u64 t; cvta.to.shared.u64 t, %1; cvt.u32.u64 %0, t; }"
      : "=r"(a) : "l"(p));
  return a;
}
__device__ __forceinline__ void ldsm_x4(uint32_t* r, uint32_t addr){
  asm volatile("ldmatrix.sync.aligned.m8n8.x4.shared.b16 {%0,%1,%2,%3}, [%4];"
    : "=r"(r[0]), "=r"(r[1]), "=r"(r[2]), "=r"(r[3]) : "r"(addr));
}
__device__ __forceinline__ void ldsm_x2(uint32_t* r, uint32_t addr){
  asm volatile("ldmatrix.sync.aligned.m8n8.x2.shared.b16 {%0,%1}, [%2];"
    : "=r"(r[0]), "=r"(r[1]) : "r"(addr));
}
__device__ __forceinline__ void mma16816(float* d, const uint32_t* a, const uint32_t* b){
  asm volatile(
    "mma.sync.aligned.m16n8k16.row.col.f32.bf16.bf16.f32 "
    "{%0,%1,%2,%3}, {%4,%5,%6,%7}, {%8,%9}, {%0,%1,%2,%3};"
    : "+f"(d[0]), "+f"(d[1]), "+f"(d[2]), "+f"(d[3])
    : "r"(a[0]), "r"(a[1]), "r"(a[2]), "r"(a[3]), "r"(b[0]), "r"(b[1]));
}

/* ---------------- Kernel 0: fp32 -> bf16 hi/lo split (bandwidth-bound) ----- */
__global__ void __launch_bounds__(256) cvt_split(
    const float* __restrict__ src, __nv_bfloat16* __restrict__ hi,
    __nv_bfloat16* __restrict__ lo, int n4)
{
  int i = blockIdx.x*256 + threadIdx.x;
  if (i >= n4) return;
  float4 v = *(const float4*)(src + (size_t)i*4);
  __nv_bfloat16 h0=__float2bfloat16(v.x), h1=__float2bfloat16(v.y),
                h2=__float2bfloat16(v.z), h3=__float2bfloat16(v.w);
  float r0=v.x-__bfloat162float(h0), r1=v.y-__bfloat162float(h1),
        r2=v.z-__bfloat162float(h2), r3=v.w-__bfloat162float(h3);
  __nv_bfloat16 l0=__float2bfloat16(r0), l1=__float2bfloat16(r1),
                l2=__float2bfloat16(r2), l3=__float2bfloat16(r3);
  u64 hw = (u64)__bfloat16_as_ushort(h0)       | ((u64)__bfloat16_as_ushort(h1)<<16)
         | ((u64)__bfloat16_as_ushort(h2)<<32) | ((u64)__bfloat16_as_ushort(h3)<<48);
  u64 lw = (u64)__bfloat16_as_ushort(l0)       | ((u64)__bfloat16_as_ushort(l1)<<16)
         | ((u64)__bfloat16_as_ushort(l2)<<32) | ((u64)__bfloat16_as_ushort(l3)<<48);
  *(u64*)(hi + (size_t)i*4) = hw;
  *(u64*)(lo + (size_t)i*4) = lw;
}

/* ---------------- Kernel A: x_gates via mma.sync bf16 3-term split ----------
 * D = A_hi.B_hi + A_hi.B_lo + A_lo.B_hi  (fp32-accurate, err ~2^-17).
 * CTA tile 128(M) x 128(N) — N doubled vs R13/R14 to amortize A fragments:
 * per warp-tile (32x64) the ldsm:mma ratio drops 24:48 -> 20:96.
 * 8 warps = 4m x 2n; warp = 2 mi x 8 ni m16n8k16 tiles; K = 8 chunks x 32. */
__global__ void __launch_bounds__(256, 1) xgates_mma(
    const float* __restrict__ bih, const float* __restrict__ bhh)
{
  __shared__ __align__(16) __nv_bfloat16 sA[2][128][APAD];  /* [hi/lo][m][k] */
  __shared__ __align__(16) __nv_bfloat16 sB[2][128][APAD];  /* [hi/lo][n][k] */
  __shared__ float bias_sm[128];

  const int tid = threadIdx.x;
  const int wid = tid >> 5, lane = tid & 31;
  const int bx = blockIdx.x, by = blockIdx.y;
  const int wm = wid >> 1, wn = wid & 1;

  if (tid < 128) bias_sm[tid] = bih[(bx<<7) + tid] + bhh[(bx<<7) + tid];

  float acc[2][8][4];
  #pragma unroll
  for (int mi=0;mi<2;mi++)
    #pragma unroll
    for (int ni=0;ni<8;ni++)
      #pragma unroll
      for (int e=0;e<4;e++) acc[mi][ni][e] = 0.f;

  const uint32_t aHi = smem_u32(&sA[0][0][0]);
  const uint32_t aLo = smem_u32(&sA[1][0][0]);
  const uint32_t bHi = smem_u32(&sB[0][0][0]);
  const uint32_t bLo = smem_u32(&sB[1][0][0]);

  /* per-thread ldmatrix address bases (byte offsets; APAD*2 = 80 B rows) */
  const int arow = wm*32 + (lane&7) + ((lane>>3)&1)*8;
  const uint32_t aoff = (uint32_t)(arow*80 + ((lane>>4)*8)*2);
  const int brow = wn*64 + (lane&7);
  const uint32_t boff = (uint32_t)(brow*80 + (((lane>>3)&1)*8)*2);

  /* staging ownership (both A and B): row = tid>>1, 16-bf16 half (tid&1) */
  const int sar = tid >> 1, sac = (tid & 1) << 4;
  const __nv_bfloat16* gAh = g_Ahi + (size_t)((by<<7) + sar)*256 + sac;
  const __nv_bfloat16* gAl = g_Alo + (size_t)((by<<7) + sar)*256 + sac;
  const __nv_bfloat16* gBh = g_Whi + (size_t)((bx<<7) + sar)*256 + sac;
  const __nv_bfloat16* gBl = g_Wlo + (size_t)((bx<<7) + sar)*256 + sac;

  for (int kc = 0; kc < 8; ++kc){
    const int k0 = kc << 5;
    {
      uint4 vh0 = *(const uint4*)(gAh + k0);
      uint4 vh1 = *(const uint4*)(gAh + k0 + 8);
      uint4 vl0 = *(const uint4*)(gAl + k0);
      uint4 vl1 = *(const uint4*)(gAl + k0 + 8);
      *(uint4*)(&sA[0][sar][sac])     = vh0;
      *(uint4*)(&sA[0][sar][sac + 8]) = vh1;
      *(uint4*)(&sA[1][sar][sac])     = vl0;
      *(uint4*)(&sA[1][sar][sac + 8]) = vl1;
      uint4 wh0 = *(const uint4*)(gBh + k0);
      uint4 wh1 = *(const uint4*)(gBh + k0 + 8);
      uint4 wl0 = *(const uint4*)(gBl + k0);
      uint4 wl1 = *(const uint4*)(gBl + k0 + 8);
      *(uint4*)(&sB[0][sar][sac])     = wh0;
      *(uint4*)(&sB[0][sar][sac + 8]) = wh1;
      *(uint4*)(&sB[1][sar][sac])     = wl0;
      *(uint4*)(&sB[1][sar][sac + 8]) = wl1;
    }
    __syncthreads();

    #pragma unroll
    for (int kh=0; kh<2; ++kh){
      const uint32_t k2 = (uint32_t)(kh<<5);    /* 16 bf16 = 32 bytes */
      uint32_t ah[2][4], al[2][4], bh[8][2], bl[8][2];
      #pragma unroll
      for (int mi=0;mi<2;mi++){
        ldsm_x4(ah[mi], aHi + aoff + (uint32_t)(mi*16*80) + k2);
        ldsm_x4(al[mi], aLo + aoff + (uint32_t)(mi*16*80) + k2);
      }
      #pragma unroll
      for (int ni=0;ni<8;ni++){
        ldsm_x2(bh[ni], bHi + boff + (uint32_t)(ni*8*80) + k2);
        ldsm_x2(bl[ni], bLo + boff + (uint32_t)(ni*8*80) + k2);
      }
      #pragma unroll
      for (int mi=0;mi<2;mi++)
        #pragma unroll
        for (int ni=0;ni<8;ni++){
          mma16816(acc[mi][ni], ah[mi], bh[ni]);
          mma16816(acc[mi][ni], ah[mi], bl[ni]);
          mma16816(acc[mi][ni], al[mi], bh[ni]);
        }
    }
    __syncthreads();
  }

  /* epilogue: D fragment rows = t/4 (+8), cols = 2*(t%4) (+1) */
  const int r0 = lane >> 2, c0 = (lane & 3) << 1;
  #pragma unroll
  for (int mi=0;mi<2;mi++){
    const int grow = (by<<7) + wm*32 + mi*16 + r0;
    #pragma unroll
    for (int ni=0;ni<8;ni++){
      const int lc = wn*64 + ni*8 + c0;
      const int gcol = (bx<<7) + lc;
      float2 o0, o1;
      o0.x = acc[mi][ni][0] + bias_sm[lc];
      o0.y = acc[mi][ni][1] + bias_sm[lc+1];
      o1.x = acc[mi][ni][2] + bias_sm[lc];
      o1.y = acc[mi][ni][3] + bias_sm[lc+1];
      *(float2*)(g_xg + (size_t)grow*GATE4 + gcol)     = o0;
      *(float2*)(g_xg + (size_t)(grow+8)*GATE4 + gcol) = o1;
    }
  }
}

/* ---------------- Kernel B: persistent recurrence (R6/R11/R13/R14, 5x) ----- */
__global__ void __launch_bounds__(REC_THREADS, 1) lstm_rec(
    const float* __restrict__ h0, const float* __restrict__ c0,
    const float* __restrict__ W_hh, float* __restrict__ out)
{
  __shared__ float h_sm[4][256];
  __shared__ float gates_sm[128*GST];

  const int tid  = threadIdx.x;
  const int blk  = blockIdx.x;
  const int bgid = blk & 15;
  const int jgid = blk >> 4;
  const int b0   = bgid*4;
  const int j0   = jgid*32;
  unsigned* barp = &g_bar16[bgid*32];

  const int wid  = tid >> 5, lane = tid & 31;
  const int lg   = lane & 15, rh = lane >> 4;

  ulonglong2 wr2[4][4];
  #pragma unroll
  for (int r=0;r<4;r++){
    const int rl = wid*8 + rh*4 + r;
    const int grow = (rl>>5)*HID + j0 + (rl&31);
    #pragma unroll
    for (int q=0;q<4;q++)
      wr2[r][q] = *(const ulonglong2*)(W_hh + (size_t)grow*HID + lg*4 + 64*q);
  }

  const int jl = tid & 31, ebi = (tid >> 5) & 3;
  const int eb = b0 + ebi, ej = j0 + jl;
  float c_reg = 0.f, xg0=0.f, xg1=0.f, xg2=0.f, xg3=0.f;
  if (tid < 128){
    c_reg = c0[eb*HID + ej];
    const float* xp = g_xg + (size_t)eb*GATE4 + ej;
    xg0 = xp[0]; xg1 = xp[HID]; xg2 = xp[2*HID]; xg3 = xp[3*HID];
  }

  for (int t=0; t<T_STEPS; ++t){
    if (t){
      const unsigned target = (unsigned)t * CHAIN_BLOCKS;
      while (ld_acq(barp) < target) { }
    }

    if (tid < 256){
      const float4* hsrc = (const float4*)(((t==0) ? h0 : g_h[t & 1]) + b0*HID);
      const int b = tid >> 6, k4 = tid & 63;
      float4 v = __ldcg(hsrc + b*64 + k4);
      *(float4*)&h_sm[b][k4*4] = v;
    }
    __syncthreads();

    #pragma unroll
    for (int b=0;b<4;b++){
      const float* hb = h_sm[b] + lg*4;
      ulonglong2 hv0 = *(const ulonglong2*)(hb);
      ulonglong2 hv1 = *(const ulonglong2*)(hb+64);
      ulonglong2 hv2 = *(const ulonglong2*)(hb+128);
      ulonglong2 hv3 = *(const ulonglong2*)(hb+192);
      float v0, v1, v2, v3;
      #pragma unroll
      for (int r=0;r<4;r++){
        u64 s0 = fmul2(wr2[r][0].x, hv0.x);
        u64 s1 = fmul2(wr2[r][0].y, hv0.y);
        s0 = ffma2(wr2[r][1].x, hv1.x, s0);
        s1 = ffma2(wr2[r][1].y, hv1.y, s1);
        s0 = ffma2(wr2[r][2].x, hv2.x, s0);
        s1 = ffma2(wr2[r][2].y, hv2.y, s1);
        s0 = ffma2(wr2[r][3].x, hv3.x, s0);
        s1 = ffma2(wr2[r][3].y, hv3.y, s1);
        float v = hadd2(fadd2(s0, s1));
        if (r==0) v0=v; else if (r==1) v1=v; else if (r==2) v2=v; else v3=v;
      }
      v0 += __shfl_xor_sync(0xffffffffu, v0, 8);
      v1 += __shfl_xor_sync(0xffffffffu, v1, 8);
      v2 += __shfl_xor_sync(0xffffffffu, v2, 8);
      v3 += __shfl_xor_sync(0xffffffffu, v3, 8);
      float a  = (lg & 8) ? v1 : v0;
      float bb = (lg & 8) ? v3 : v2;
      a  += __shfl_xor_sync(0xffffffffu, a, 4);
      bb += __shfl_xor_sync(0xffffffffu, bb, 4);
      float x = (lg & 4) ? bb : a;
      x += __shfl_xor_sync(0xffffffffu, x, 2);
      x += __shfl_xor_sync(0xffffffffu, x, 1);
      if ((lg & 3) == 0){
        const int rsel = ((lg>>3)&1) | (((lg>>2)&1)<<1);
        gates_sm[(wid*8 + rh*4 + rsel)*GST + b] = x;
      }
    }
    __syncthreads();

    float hn = 0.f;
    if (tid < 128){
      float pi = gates_sm[(0*32+jl)*GST + ebi] + xg0;
      float pf = gates_sm[(1*32+jl)*GST + ebi] + xg1;
      float pg = gates_sm[(2*32+jl)*GST + ebi] + xg2;
      float po = gates_sm[(3*32+jl)*GST + ebi] + xg3;
      float ii = fsigm(pi), ff = fsigm(pf), gg = ftanh(pg), oo = fsigm(po);
      c_reg = ff*c_reg + ii*gg;
      hn = oo * ftanh(c_reg);
      __stcg(&g_h[(t+1)&1][eb*HID + ej], hn);
    }
    __syncthreads();

    if (tid == 0) red_rel_add(barp, 1u);
    if (tid < 128){
      out[(size_t)t*NG + eb*HID + ej] = hn;
      if (t == T_STEPS-1){
        out[(size_t)T_STEPS*NG + eb*HID + ej]      = hn;
        out[(size_t)T_STEPS*NG + NG + eb*HID + ej] = c_reg;
      } else {
        const float* xp = g_xg + ((size_t)(t+1)*BATCH + eb)*GATE4 + ej;
        xg0 = xp[0]; xg1 = xp[HID]; xg2 = xp[2*HID]; xg3 = xp[3*HID];
      }
    }
  }

  if (tid == 0){
    __threadfence();
    unsigned prev = atomicAdd(&g_done, 1u);
    if (prev == REC_BLOCKS-1){
      #pragma unroll
      for (int ch=0; ch<16; ch++) g_bar16[ch*32] = 0u;
      g_done = 0u;
      __threadfence();
    }
  }
}

extern "C" void kernel_launch(void* const* d_in, const int* in_sizes, int n_in,
                              void* d_out, int out_size)
{
  (void)in_sizes; (void)n_in; (void)out_size;
  const float* input = (const float*)d_in[0];
  const float* h0    = (const float*)d_in[1];
  const float* c0    = (const float*)d_in[2];
  const float* W_ih  = (const float*)d_in[3];
  const float* W_hh  = (const float*)d_in[4];
  const float* b_ih  = (const float*)d_in[5];
  const float* b_hh  = (const float*)d_in[6];
  float* out = (float*)d_out;

  __nv_bfloat16 *ahi, *alo, *whi, *wlo;
  cudaGetSymbolAddress((void**)&ahi, g_Ahi);
  cudaGetSymbolAddress((void**)&alo, g_Alo);
  cudaGetSymbolAddress((void**)&whi, g_Whi);
  cudaGetSymbolAddress((void**)&wlo, g_Wlo);

  cvt_split<<<(M_ALL*256/4 + 255)/256, 256>>>(input, ahi, alo, M_ALL*256/4);
  cvt_split<<<(GATE4*256/4 + 255)/256, 256>>>(W_ih, whi, wlo, GATE4*256/4);
  xgates_mma<<<dim3(8,1024), 256>>>(b_ih, b_hh);
  lstm_rec<<<REC_BLOCKS, REC_THREADS>>>(h0, c0, W_hh, out);
}

// round 16
// speedup vs baseline: 1.0277x; 1.0277x over previous
#include <cuda_runtime.h>
#include <cuda_bf16.h>
#include <math.h>
#include <stdint.h>

#define T_STEPS 2048
#define BATCH   64
#define HID     256
#define GATE4   1024
#define NG      (BATCH*HID)          /* 16384 */
#define REC_BLOCKS 128
#define REC_THREADS 512
#define CHAIN_BLOCKS 8
#define APAD    40                   /* bf16 row stride: 80B, conflict-free */

typedef unsigned long long u64;

/* Scratch (device globals: no allocation allowed in kernel_launch) */
__device__ float g_xg[134217728];    /* [T][B][4H] precomputed input gates */
__device__ float g_h[2][NG];         /* double-buffered recurrent h */
__device__ unsigned g_bar16[512];    /* 16 chain barriers, 128B apart */
__device__ unsigned g_done;          /* end-of-kernel reset rendezvous */

/* ---- packed f32x2 helpers (recurrence) ---- */
__device__ __forceinline__ u64 ffma2(u64 a, u64 b, u64 c){
  u64 d; asm("fma.rn.f32x2 %0, %1, %2, %3;" : "=l"(d) : "l"(a), "l"(b), "l"(c));
  return d;
}
__device__ __forceinline__ u64 fmul2(u64 a, u64 b){
  u64 d; asm("mul.rn.f32x2 %0, %1, %2;" : "=l"(d) : "l"(a), "l"(b));
  return d;
}
__device__ __forceinline__ u64 fadd2(u64 a, u64 b){
  u64 d; asm("add.rn.f32x2 %0, %1, %2;" : "=l"(d) : "l"(a), "l"(b));
  return d;
}
__device__ __forceinline__ float hadd2(u64 a){
  unsigned lo, hi;
  asm("mov.b64 {%0, %1}, %2;" : "=r"(lo), "=r"(hi) : "l"(a));
  return __uint_as_float(lo) + __uint_as_float(hi);
}
__device__ __forceinline__ float fsigm(float x){
  return __fdividef(1.f, 1.f + __expf(-x));
}
__device__ __forceinline__ float ftanh(float x){
  return __fdividef(2.f, 1.f + __expf(-2.f*x)) - 1.f;
}
__device__ __forceinline__ unsigned ld_acq(const unsigned* p){
  unsigned v;
  asm volatile("ld.global.acquire.gpu.u32 %0, [%1];" : "=r"(v) : "l"(p) : "memory");
  return v;
}
__device__ __forceinline__ void red_rel_add(unsigned* p, unsigned v){
  asm volatile("red.release.gpu.global.add.u32 [%0], %1;" :: "l"(p), "r"(v) : "memory");
}

/* ---- HMMA / ldmatrix helpers (baseline PTX, valid on compute_103) ---- */
__device__ __forceinline__ uint32_t smem_u32(const void* p){
  uint32_t a;
  asm("{ .reg .u64 t; cvta.to.shared.u64 t, %1; cvt.u32.u64 %0, t; }"
      : "=r"(a) : "l"(p));
  return a;
}
__device__ __forceinline__ void ldsm_x4(uint32_t* r, uint32_t addr){
  asm volatile("ldmatrix.sync.aligned.m8n8.x4.shared.b16 {%0,%1,%2,%3}, [%4];"
    : "=r"(r[0]), "=r"(r[1]), "=r"(r[2]), "=r"(r[3]) : "r"(addr));
}
__device__ __forceinline__ void ldsm_x2(uint32_t* r, uint32_t addr){
  asm volatile("ldmatrix.sync.aligned.m8n8.x2.shared.b16 {%0,%1}, [%2];"
    : "=r"(r[0]), "=r"(r[1]) : "r"(addr));
}
__device__ __forceinline__ void mma16816(float* d, const uint32_t* a, const uint32_t* b){
  asm volatile(
    "mma.sync.aligned.m16n8k16.row.col.f32.bf16.bf16.f32 "
    "{%0,%1,%2,%3}, {%4,%5,%6,%7}, {%8,%9}, {%0,%1,%2,%3};"
    : "+f"(d[0]), "+f"(d[1]), "+f"(d[2]), "+f"(d[3])
    : "r"(a[0]), "r"(a[1]), "r"(a[2]), "r"(a[3]), "r"(b[0]), "r"(b[1]));
}
/* split 4 consecutive fp32 k-values into bf16 hi/lo and store as u64 pairs */
__device__ __forceinline__ void split40(__nv_bfloat16* hi, __nv_bfloat16* lo,
                                        int row, int col, float4 v){
  __nv_bfloat16 h0=__float2bfloat16(v.x), h1=__float2bfloat16(v.y),
                h2=__float2bfloat16(v.z), h3=__float2bfloat16(v.w);
  float r0=v.x-__bfloat162float(h0), r1=v.y-__bfloat162float(h1),
        r2=v.z-__bfloat162float(h2), r3=v.w-__bfloat162float(h3);
  __nv_bfloat16 l0=__float2bfloat16(r0), l1=__float2bfloat16(r1),
                l2=__float2bfloat16(r2), l3=__float2bfloat16(r3);
  u64 hw = (u64)__bfloat16_as_ushort(h0)       | ((u64)__bfloat16_as_ushort(h1)<<16)
         | ((u64)__bfloat16_as_ushort(h2)<<32) | ((u64)__bfloat16_as_ushort(h3)<<48);
  u64 lw = (u64)__bfloat16_as_ushort(l0)       | ((u64)__bfloat16_as_ushort(l1)<<16)
         | ((u64)__bfloat16_as_ushort(l2)<<32) | ((u64)__bfloat16_as_ushort(l3)<<48);
  *(u64*)(hi + row*APAD + col) = hw;
  *(u64*)(lo + row*APAD + col) = lw;
}

/* ---------------- Kernel A: x_gates via mma.sync bf16 3-term split ----------
 * BYTE-EXACT revert to R13 (best measured GEMM: ~1.40ms). */
__global__ void __launch_bounds__(256) xgates_mma(
    const float* __restrict__ A, const float* __restrict__ W,
    const float* __restrict__ bih, const float* __restrict__ bhh)
{
  __shared__ __align__(16) __nv_bfloat16 sA[2][128][APAD];  /* [hi/lo][m][k] */
  __shared__ __align__(16) __nv_bfloat16 sB[2][64][APAD];   /* [hi/lo][n][k] */
  __shared__ float bias_sm[64];

  const int tid = threadIdx.x;
  const int wid = tid >> 5, lane = tid & 31;
  const int bx = blockIdx.x, by = blockIdx.y;
  const int wm = wid >> 1, wn = wid & 1;

  if (tid < 64) bias_sm[tid] = bih[(bx<<6) + tid] + bhh[(bx<<6) + tid];

  float acc[2][4][4];
  #pragma unroll
  for (int mi=0;mi<2;mi++)
    #pragma unroll
    for (int ni=0;ni<4;ni++)
      #pragma unroll
      for (int e=0;e<4;e++) acc[mi][ni][e] = 0.f;

  const uint32_t aHi = smem_u32(&sA[0][0][0]);
  const uint32_t aLo = smem_u32(&sA[1][0][0]);
  const uint32_t bHi = smem_u32(&sB[0][0][0]);
  const uint32_t bLo = smem_u32(&sB[1][0][0]);

  const int arow = wm*32 + (lane&7) + ((lane>>3)&1)*8;
  const uint32_t aoff = (uint32_t)(arow*80 + ((lane>>4)*8)*2);
  const int brow = wn*32 + (lane&7);
  const uint32_t boff = (uint32_t)(brow*80 + (((lane>>3)&1)*8)*2);

  const float* Ab = A + (size_t)(by<<7)*256;
  const float* Wb = W + (size_t)(bx<<6)*256;

  for (int kc = 0; kc < 8; ++kc){
    {
      const int row = tid >> 1, ch = (tid & 1) << 4;
      const float* src = Ab + (size_t)row*256 + (kc<<5) + ch;
      #pragma unroll
      for (int q=0;q<4;q++)
        split40(&sA[0][0][0], &sA[1][0][0], row, ch + (q<<2),
                *(const float4*)(src + (q<<2)));
    }
    {
      const int row = tid >> 2, ch = (tid & 3) << 3;
      const float* src = Wb + (size_t)row*256 + (kc<<5) + ch;
      #pragma unroll
      for (int q=0;q<2;q++)
        split40(&sB[0][0][0], &sB[1][0][0], row, ch + (q<<2),
                *(const float4*)(src + (q<<2)));
    }
    __syncthreads();

    #pragma unroll
    for (int kh=0; kh<2; ++kh){
      const uint32_t k2 = (uint32_t)(kh<<5);
      uint32_t ah[2][4], al[2][4], bh[4][2], bl[4][2];
      #pragma unroll
      for (int mi=0;mi<2;mi++){
        ldsm_x4(ah[mi], aHi + aoff + (uint32_t)(mi*16*80) + k2);
        ldsm_x4(al[mi], aLo + aoff + (uint32_t)(mi*16*80) + k2);
      }
      #pragma unroll
      for (int ni=0;ni<4;ni++){
        ldsm_x2(bh[ni], bHi + boff + (uint32_t)(ni*8*80) + k2);
        ldsm_x2(bl[ni], bLo + boff + (uint32_t)(ni*8*80) + k2);
      }
      #pragma unroll
      for (int mi=0;mi<2;mi++)
        #pragma unroll
        for (int ni=0;ni<4;ni++){
          mma16816(acc[mi][ni], ah[mi], bh[ni]);
          mma16816(acc[mi][ni], ah[mi], bl[ni]);
          mma16816(acc[mi][ni], al[mi], bh[ni]);
        }
    }
    __syncthreads();
  }

  const int r0 = lane >> 2, c0 = (lane & 3) << 1;
  #pragma unroll
  for (int mi=0;mi<2;mi++){
    const int grow = (by<<7) + wm*32 + mi*16 + r0;
    #pragma unroll
    for (int ni=0;ni<4;ni++){
      const int lc = wn*32 + ni*8 + c0;
      const int gcol = (bx<<6) + lc;
      float2 o0, o1;
      o0.x = acc[mi][ni][0] + bias_sm[lc];
      o0.y = acc[mi][ni][1] + bias_sm[lc+1];
      o1.x = acc[mi][ni][2] + bias_sm[lc];
      o1.y = acc[mi][ni][3] + bias_sm[lc+1];
      *(float2*)(g_xg + (size_t)grow*GATE4 + gcol)     = o0;
      *(float2*)(g_xg + (size_t)(grow+8)*GATE4 + gcol) = o1;
    }
  }
}

/* ---------------- Kernel B: persistent recurrence, in-warp epilogue --------
 * 16 chains x 8 blocks (geometry/protocol as R6). NEW: warp wid owns ALL 4
 * gates of its 2 hidden units (rows = gate*32 + wid*2 + jj), so after the
 * k-reduction the SAME warp runs the epilogue from a private 40-float smem
 * strip: no cross-warp gates traffic, one __syncthreads removed.
 * Remaining per step: poll -> stage h (+sync) -> compute/reduce -> warp STS
 * + syncwarp + epilogue (lanes 0-7) -> syncthreads -> tid0 release-arrive
 * (proven pattern) -> out-stores + xg prefetch in shadow. */
__global__ void __launch_bounds__(REC_THREADS, 1) lstm_rec(
    const float* __restrict__ h0, const float* __restrict__ c0,
    const float* __restrict__ W_hh, float* __restrict__ out)
{
  __shared__ float h_sm[4][256];         /* [local batch][k] : 4KB */
  __shared__ float gates_sm[16*40];      /* per-warp strip: [ri*5 + b] */

  const int tid  = threadIdx.x;
  const int blk  = blockIdx.x;
  const int bgid = blk & 15;             /* chain id (batch group) */
  const int jgid = blk >> 4;             /* j-group within chain   */
  const int b0   = bgid*4;
  const int j0   = jgid*32;
  unsigned* barp = &g_bar16[bgid*32];

  const int wid  = tid >> 5, lane = tid & 31;
  const int lg   = lane & 15, rh = lane >> 4;

  /* W_hh rows -> registers. r=0..3: ri = rh*4+r; gate = ri>>1; jj = ri&1;
   * grow = gate*HID + j0 + wid*2 + jj  (warp owns 2 j x 4 gates). */
  ulonglong2 wr2[4][4];
  #pragma unroll
  for (int r=0;r<4;r++){
    const int ri = rh*4 + r;
    const int grow = (ri>>1)*HID + j0 + wid*2 + (ri&1);
    #pragma unroll
    for (int q=0;q<4;q++)
      wr2[r][q] = *(const ulonglong2*)(W_hh + (size_t)grow*HID + lg*4 + 64*q);
  }

  /* epilogue ownership: lanes 0-7 of each warp: jj = lane>>2, b = lane&3 */
  const int ejj = (lane >> 2) & 1, ebl = lane & 3;
  const int ej = j0 + wid*2 + ejj, eb = b0 + ebl;
  const bool epi = (lane < 8);
  float c_reg = 0.f, xg0=0.f, xg1=0.f, xg2=0.f, xg3=0.f;
  if (epi){
    c_reg = c0[eb*HID + ej];
    const float* xp = g_xg + (size_t)eb*GATE4 + ej;   /* t = 0 */
    xg0 = xp[0]; xg1 = xp[HID]; xg2 = xp[2*HID]; xg3 = xp[3*HID];
  }
  float* gw = gates_sm + wid*40;

  for (int t=0; t<T_STEPS; ++t){
    /* ---- wait for previous step's h from this chain (acquire) */
    if (t){
      const unsigned target = (unsigned)t * CHAIN_BLOCKS;
      while (ld_acq(barp) < target) { }
    }

    /* ---- stage h: 4 batches x 256 = 4KB, tid<256 one float4 each (.cg) */
    if (tid < 256){
      const float4* hsrc = (const float4*)(((t==0) ? h0 : g_h[t & 1]) + b0*HID);
      const int b = tid >> 6, k4 = tid & 63;
      float4 v = __ldcg(hsrc + b*64 + k4);
      *(float4*)&h_sm[b][k4*4] = v;
    }
    __syncthreads();

    /* ---- compute: 4 batch passes; 8 rows per warp (rh picks 4), FFMA2 */
    #pragma unroll
    for (int b=0;b<4;b++){
      const float* hb = h_sm[b] + lg*4;
      ulonglong2 hv0 = *(const ulonglong2*)(hb);
      ulonglong2 hv1 = *(const ulonglong2*)(hb+64);
      ulonglong2 hv2 = *(const ulonglong2*)(hb+128);
      ulonglong2 hv3 = *(const ulonglong2*)(hb+192);
      float v0, v1, v2, v3;
      #pragma unroll
      for (int r=0;r<4;r++){
        u64 s0 = fmul2(wr2[r][0].x, hv0.x);
        u64 s1 = fmul2(wr2[r][0].y, hv0.y);
        s0 = ffma2(wr2[r][1].x, hv1.x, s0);
        s1 = ffma2(wr2[r][1].y, hv1.y, s1);
        s0 = ffma2(wr2[r][2].x, hv2.x, s0);
        s1 = ffma2(wr2[r][2].y, hv2.y, s1);
        s0 = ffma2(wr2[r][3].x, hv3.x, s0);
        s1 = ffma2(wr2[r][3].y, hv3.y, s1);
        float v = hadd2(fadd2(s0, s1));
        if (r==0) v0=v; else if (r==1) v1=v; else if (r==2) v2=v; else v3=v;
      }
      /* reduce 4 rows over the 16 k-lanes: 8 SHFL (rh bit untouched) */
      v0 += __shfl_xor_sync(0xffffffffu, v0, 8);
      v1 += __shfl_xor_sync(0xffffffffu, v1, 8);
      v2 += __shfl_xor_sync(0xffffffffu, v2, 8);
      v3 += __shfl_xor_sync(0xffffffffu, v3, 8);
      float a  = (lg & 8) ? v1 : v0;
      float bb = (lg & 8) ? v3 : v2;
      a  += __shfl_xor_sync(0xffffffffu, a, 4);
      bb += __shfl_xor_sync(0xffffffffu, bb, 4);
      float x = (lg & 4) ? bb : a;
      x += __shfl_xor_sync(0xffffffffu, x, 2);
      x += __shfl_xor_sync(0xffffffffu, x, 1);
      if ((lg & 3) == 0){
        const int rsel = ((lg>>3)&1) | (((lg>>2)&1)<<1);   /* 0,8,4,12 -> 0..3 */
        gw[(rh*4 + rsel)*5 + b] = x;
      }
    }
    __syncwarp();

    /* ---- in-warp epilogue: lanes 0-7 own (jj, b); all 4 gates local */
    float hn = 0.f;
    if (epi){
      float pi = gw[(0*2 + ejj)*5 + ebl] + xg0;
      float pf = gw[(1*2 + ejj)*5 + ebl] + xg1;
      float pg = gw[(2*2 + ejj)*5 + ebl] + xg2;
      float po = gw[(3*2 + ejj)*5 + ebl] + xg3;
      float ii = fsigm(pi), ff = fsigm(pf), gg = ftanh(pg), oo = fsigm(po);
      c_reg = ff*c_reg + ii*gg;
      hn = oo * ftanh(c_reg);
      __stcg(&g_h[(t+1)&1][eb*HID + ej], hn);
    }
    __syncthreads();   /* h stores observed CTA-wide before tid0's release */

    /* ---- arrival (release), then out-stores + prefetch in its shadow */
    if (tid == 0) red_rel_add(barp, 1u);
    if (epi){
      out[(size_t)t*NG + eb*HID + ej] = hn;
      if (t == T_STEPS-1){
        out[(size_t)T_STEPS*NG + eb*HID + ej]      = hn;     /* h_T */
        out[(size_t)T_STEPS*NG + NG + eb*HID + ej] = c_reg;  /* c_T */
      } else {
        const float* xp = g_xg + ((size_t)(t+1)*BATCH + eb)*GATE4 + ej;
        xg0 = xp[0]; xg1 = xp[HID]; xg2 = xp[2*HID]; xg3 = xp[3*HID];
      }
    }
  }

  /* reset counters for the next graph replay: last block to arrive does it */
  if (tid == 0){
    __threadfence();
    unsigned prev = atomicAdd(&g_done, 1u);
    if (prev == REC_BLOCKS-1){
      #pragma unroll
      for (int ch=0; ch<16; ch++) g_bar16[ch*32] = 0u;
      g_done = 0u;
      __threadfence();
    }
  }
}

extern "C" void kernel_launch(void* const* d_in, const int* in_sizes, int n_in,
                              void* d_out, int out_size)
{
  (void)in_sizes; (void)n_in; (void)out_size;
  const float* input = (const float*)d_in[0];
  const float* h0    = (const float*)d_in[1];
  const float* c0    = (const float*)d_in[2];
  const float* W_ih  = (const float*)d_in[3];
  const float* W_hh  = (const float*)d_in[4];
  const float* b_ih  = (const float*)d_in[5];
  const float* b_hh  = (const float*)d_in[6];
  float* out = (float*)d_out;

  xgates_mma<<<dim3(16,1024), 256>>>(input, W_ih, b_ih, b_hh);
  lstm_rec<<<REC_BLOCKS, REC_THREADS>>>(h0, c0, W_hh, out);
}